// round 1
// baseline (speedup 1.0000x reference)
#include <cuda_runtime.h>
#include <math.h>

#define NNODES 10000
#define NPAD   10112      // 79 * 128
#define EDGES  80000
#define HID    1024
#define NLAYERS 4

// ---------------- scratch (static device globals: allowed) ----------------
__device__ float g_H[(size_t)NPAD * HID];            // node features (ping)
__device__ float g_S[(size_t)NPAD * HID];            // aggregated relu sums
__device__ float g_C1[(size_t)NPAD * 2 * HID];       // [A | B] per node
__device__ float g_Wcat[(size_t)NLAYERS * HID * 2 * HID]; // [W1a-W1b | W1b]
__device__ float g_G1[(size_t)NPAD * 256];           // ghost hidden
__device__ int   g_deg[NPAD];
__device__ int   g_rowptr[NNODES + 1];
__device__ int   g_cursor[NNODES];
__device__ int   g_csrsrc[EDGES];

// ---------------- helpers ----------------
__device__ __forceinline__ unsigned f2tf32(float f) {
    unsigned r;
    asm("cvt.rna.tf32.f32 %0, %1;" : "=r"(r) : "f"(f));
    return r;
}

#define MMA_TF32(d, a, b)                                              \
    asm volatile(                                                      \
        "mma.sync.aligned.m16n8k8.row.col.f32.tf32.tf32.f32 "          \
        "{%0,%1,%2,%3}, {%4,%5,%6,%7}, {%8,%9}, {%0,%1,%2,%3};\n"      \
        : "+f"(d[0]), "+f"(d[1]), "+f"(d[2]), "+f"(d[3])               \
        : "r"(a[0]), "r"(a[1]), "r"(a[2]), "r"(a[3]),                  \
          "r"(b[0]), "r"(b[1]))

// ---------------- weight prep: Wcat = [W1a - W1b | W1b] ----------------
__global__ void wcat_kernel(const float* __restrict__ W1) {
    size_t idx = (size_t)blockIdx.x * 256 + threadIdx.x;
    const size_t TOT = (size_t)NLAYERS * HID * 2 * HID;
    if (idx >= TOT) return;
    int l = (int)(idx / ((size_t)HID * 2 * HID));
    size_t rem = idx % ((size_t)HID * 2 * HID);
    int k = (int)(rem / (2 * HID));
    int j = (int)(rem % (2 * HID));
    const float* Wl = W1 + (size_t)l * 2 * HID * HID;
    float v;
    if (j < HID)
        v = Wl[(size_t)k * HID + j] - Wl[(size_t)(HID + k) * HID + j];
    else
        v = Wl[(size_t)(HID + k) * HID + (j - HID)];
    g_Wcat[idx] = v;
}

// ---------------- CSR build ----------------
__global__ void zero_deg_kernel() {
    int i = blockIdx.x * 256 + threadIdx.x;
    if (i < NPAD) g_deg[i] = 0;
}

__global__ void hist_kernel(const int* __restrict__ ei) {
    int e = blockIdx.x * 256 + threadIdx.x;
    if (e < EDGES) atomicAdd(&g_deg[ei[EDGES + e]], 1);  // dst row
}

__global__ void scan_kernel() {
    const int CH = 10;  // 1024 * 10 >= 10000
    int t = threadIdx.x;
    int base = t * CH;
    int loc[CH];
    int s = 0;
#pragma unroll
    for (int c = 0; c < CH; c++) {
        int idx = base + c;
        int v = (idx < NNODES) ? g_deg[idx] : 0;
        loc[c] = s;
        s += v;
    }
    __shared__ int sm[1024];
    sm[t] = s;
    __syncthreads();
    for (int off = 1; off < 1024; off <<= 1) {
        int v = (t >= off) ? sm[t - off] : 0;
        __syncthreads();
        sm[t] += v;
        __syncthreads();
    }
    int excl = (t > 0) ? sm[t - 1] : 0;
#pragma unroll
    for (int c = 0; c < CH; c++) {
        int idx = base + c;
        if (idx < NNODES) {
            int rp = excl + loc[c];
            g_rowptr[idx] = rp;
            g_cursor[idx] = rp;
        }
    }
    if (t == 1023) g_rowptr[NNODES] = sm[1023];
}

__global__ void scatter_kernel(const int* __restrict__ ei) {
    int e = blockIdx.x * 256 + threadIdx.x;
    if (e >= EDGES) return;
    int d = ei[EDGES + e];
    int s = ei[e];
    int p = atomicAdd(&g_cursor[d], 1);
    g_csrsrc[p] = s;
}

// ---------------- initial embedding: h = sin(x@proj_w) * cos(x@proj_w) ----------------
__global__ void proj_kernel(const float* __restrict__ x, const float* __restrict__ pw) {
    int n = blockIdx.x;
    int tid = threadIdx.x;  // 256 threads, 4 floats each
    float4* Hout = (float4*)(g_H + (size_t)n * HID);
    if (n >= NNODES) {
        Hout[tid] = make_float4(0.f, 0.f, 0.f, 0.f);
        return;
    }
    __shared__ float xs[18];
    if (tid < 18) xs[tid] = x[n * 18 + tid];
    __syncthreads();
    float4 acc = make_float4(0.f, 0.f, 0.f, 0.f);
#pragma unroll
    for (int t = 0; t < 18; t++) {
        float4 w = ((const float4*)(pw + (size_t)t * HID))[tid];
        float xv = xs[t];
        acc.x += xv * w.x;
        acc.y += xv * w.y;
        acc.z += xv * w.z;
        acc.w += xv * w.w;
    }
    float4 h;
    h.x = sinf(acc.x) * cosf(acc.x);
    h.y = sinf(acc.y) * cosf(acc.y);
    h.z = sinf(acc.z) * cosf(acc.z);
    h.w = sinf(acc.w) * cosf(acc.w);
    Hout[tid] = h;
}

// ---------------- edge aggregation: S[i] = sum_e relu(A[i] + B[src_e] + b1) ----------------
__global__ void edge_agg_kernel(const float* __restrict__ b1) {
    int i = blockIdx.x;
    int tid = threadIdx.x;  // 256 threads, 4 floats each
    float4* Sout = (float4*)(g_S + (size_t)i * HID);
    if (i >= NNODES) {
        Sout[tid] = make_float4(0.f, 0.f, 0.f, 0.f);
        return;
    }
    float4 a = ((const float4*)(g_C1 + (size_t)i * 2 * HID))[tid];
    float4 bb = ((const float4*)b1)[tid];
    a.x += bb.x; a.y += bb.y; a.z += bb.z; a.w += bb.w;
    float4 acc = make_float4(0.f, 0.f, 0.f, 0.f);
    int p0 = g_rowptr[i], p1 = g_rowptr[i + 1];
    for (int p = p0; p < p1; p++) {
        int s = g_csrsrc[p];
        float4 b = ((const float4*)(g_C1 + (size_t)s * 2 * HID + HID))[tid];
        acc.x += fmaxf(a.x + b.x, 0.f);
        acc.y += fmaxf(a.y + b.y, 0.f);
        acc.z += fmaxf(a.z + b.z, 0.f);
        acc.w += fmaxf(a.w + b.w, 0.f);
    }
    Sout[tid] = acc;
}

// ---------------- TF32 GEMM: C[M,N] = A[M,K] @ B[K,N], M = grid.y*128 ----------------
// epi: 0 = none, 1 = relu, 2 = relu(acc + deg[m]*bias[n]), 3 = relu(acc + bias[n])
__global__ __launch_bounds__(128) void gemm_tf32_kernel(
    const float* __restrict__ A, const float* __restrict__ B, float* __restrict__ C,
    int K, int N, int epi, const float* __restrict__ bias, const int* __restrict__ deg)
{
    __shared__ float As[128][36];   // [m][k], pad 4 -> conflict-free frag loads
    __shared__ float Bs[32][136];   // [k][n], pad 8 -> conflict-free frag loads

    int tid = threadIdx.x;
    int warp = tid >> 5, lane = tid & 31;
    int lr = lane >> 2, lc = lane & 3;      // groupID, threadID-in-group
    int moff = (warp >> 1) * 64, noff = (warp & 1) * 64;
    int gm0 = blockIdx.y * 128, gn0 = blockIdx.x * 128;

    float acc[4][8][4];
#pragma unroll
    for (int mf = 0; mf < 4; mf++)
#pragma unroll
        for (int nf = 0; nf < 8; nf++)
#pragma unroll
            for (int q = 0; q < 4; q++) acc[mf][nf][q] = 0.f;

    for (int kt = 0; kt < K; kt += 32) {
        // load A tile 128x32 (8 float4 per thread)
#pragma unroll
        for (int i = 0; i < 8; i++) {
            int idx = tid + i * 128;
            int r = idx >> 3, c4 = (idx & 7) << 2;
            float4 v = *(const float4*)(A + (size_t)(gm0 + r) * K + kt + c4);
            As[r][c4 + 0] = __uint_as_float(f2tf32(v.x));
            As[r][c4 + 1] = __uint_as_float(f2tf32(v.y));
            As[r][c4 + 2] = __uint_as_float(f2tf32(v.z));
            As[r][c4 + 3] = __uint_as_float(f2tf32(v.w));
        }
        // load B tile 32x128
#pragma unroll
        for (int i = 0; i < 8; i++) {
            int idx = tid + i * 128;
            int r = idx >> 5, c4 = (idx & 31) << 2;
            float4 v = *(const float4*)(B + (size_t)(kt + r) * N + gn0 + c4);
            Bs[r][c4 + 0] = __uint_as_float(f2tf32(v.x));
            Bs[r][c4 + 1] = __uint_as_float(f2tf32(v.y));
            Bs[r][c4 + 2] = __uint_as_float(f2tf32(v.z));
            Bs[r][c4 + 3] = __uint_as_float(f2tf32(v.w));
        }
        __syncthreads();

#pragma unroll
        for (int ks = 0; ks < 4; ks++) {
            int kb = ks * 8;
            unsigned a[4][4], b[8][2];
#pragma unroll
            for (int mf = 0; mf < 4; mf++) {
                int r = moff + mf * 16 + lr;
                a[mf][0] = __float_as_uint(As[r][kb + lc]);
                a[mf][1] = __float_as_uint(As[r + 8][kb + lc]);
                a[mf][2] = __float_as_uint(As[r][kb + lc + 4]);
                a[mf][3] = __float_as_uint(As[r + 8][kb + lc + 4]);
            }
#pragma unroll
            for (int nf = 0; nf < 8; nf++) {
                int c = noff + nf * 8 + lr;
                b[nf][0] = __float_as_uint(Bs[kb + lc][c]);
                b[nf][1] = __float_as_uint(Bs[kb + lc + 4][c]);
            }
#pragma unroll
            for (int mf = 0; mf < 4; mf++)
#pragma unroll
                for (int nf = 0; nf < 8; nf++)
                    MMA_TF32(acc[mf][nf], a[mf], b[nf]);
        }
        __syncthreads();
    }

    // epilogue
#pragma unroll
    for (int mf = 0; mf < 4; mf++) {
        int r = gm0 + moff + mf * 16 + lr;
        float d0 = 0.f, d1 = 0.f;
        if (epi == 2) { d0 = (float)deg[r]; d1 = (float)deg[r + 8]; }
#pragma unroll
        for (int nf = 0; nf < 8; nf++) {
            int c = gn0 + noff + nf * 8 + 2 * lc;
            float2 v0 = make_float2(acc[mf][nf][0], acc[mf][nf][1]);
            float2 v1 = make_float2(acc[mf][nf][2], acc[mf][nf][3]);
            if (epi != 0) {
                if (epi == 2) {
                    float b0 = bias[c], b1v = bias[c + 1];
                    v0.x += d0 * b0; v0.y += d0 * b1v;
                    v1.x += d1 * b0; v1.y += d1 * b1v;
                } else if (epi == 3) {
                    float b0 = bias[c], b1v = bias[c + 1];
                    v0.x += b0; v0.y += b1v;
                    v1.x += b0; v1.y += b1v;
                }
                v0.x = fmaxf(v0.x, 0.f); v0.y = fmaxf(v0.y, 0.f);
                v1.x = fmaxf(v1.x, 0.f); v1.y = fmaxf(v1.y, 0.f);
            }
            *(float2*)(C + (size_t)r * N + c) = v0;
            *(float2*)(C + (size_t)(r + 8) * N + c) = v1;
        }
    }
}

// ---------------- final heads ----------------
// out: [0,10000) ghost, [10000,190000) stable (N x 18), [190000, ...) h (N x 1024)
__global__ void final_kernel(const float* __restrict__ gw2, const float* __restrict__ gb2,
                             const float* __restrict__ sw, const float* __restrict__ sb,
                             float* __restrict__ out)
{
    int n = blockIdx.x;
    int tid = threadIdx.x;
    int lane = tid & 31, w = tid >> 5;

    // ghost score: reduce G1[n,:] * gw2
    float v = g_G1[(size_t)n * 256 + tid] * gw2[tid];
#pragma unroll
    for (int o = 16; o; o >>= 1) v += __shfl_down_sync(0xffffffffu, v, o);
    __shared__ float gs[8];
    if (lane == 0) gs[w] = v;

    // h copy + stable state partials
    float4 hv = ((const float4*)(g_H + (size_t)n * HID))[tid];
    ((float4*)(out + 190000 + (size_t)n * HID))[tid] = hv;

    int k = tid * 4;
    float sacc[18];
#pragma unroll
    for (int j = 0; j < 18; j++) {
        sacc[j] = hv.x * sw[(size_t)(k + 0) * 18 + j]
                + hv.y * sw[(size_t)(k + 1) * 18 + j]
                + hv.z * sw[(size_t)(k + 2) * 18 + j]
                + hv.w * sw[(size_t)(k + 3) * 18 + j];
    }
#pragma unroll
    for (int j = 0; j < 18; j++)
#pragma unroll
        for (int o = 16; o; o >>= 1) sacc[j] += __shfl_down_sync(0xffffffffu, sacc[j], o);

    __shared__ float sp[8][18];
    if (lane == 0)
#pragma unroll
        for (int j = 0; j < 18; j++) sp[w][j] = sacc[j];
    __syncthreads();

    if (tid == 0) {
        float g = 0.f;
#pragma unroll
        for (int i = 0; i < 8; i++) g += gs[i];
        g += gb2[0];
        out[n] = 1.f / (1.f + expf(-g));
    }
    if (tid < 18) {
        float s = sb[tid];
#pragma unroll
        for (int i = 0; i < 8; i++) s += sp[i][tid];
        out[10000 + n * 18 + tid] = s;
    }
}

// ---------------- launch ----------------
extern "C" void kernel_launch(void* const* d_in, const int* in_sizes, int n_in,
                              void* d_out, int out_size)
{
    const float* x      = (const float*)d_in[0];
    const int*   ei     = (const int*)d_in[1];
    const float* proj_w = (const float*)d_in[2];
    const float* W1     = (const float*)d_in[3];
    const float* b1     = (const float*)d_in[4];
    const float* W2     = (const float*)d_in[5];
    const float* b2     = (const float*)d_in[6];
    const float* gw1    = (const float*)d_in[7];
    const float* gb1    = (const float*)d_in[8];
    const float* gw2    = (const float*)d_in[9];
    const float* gb2    = (const float*)d_in[10];
    const float* sw     = (const float*)d_in[11];
    const float* sb     = (const float*)d_in[12];
    float* out = (float*)d_out;

    float *H, *S, *C1, *Wc, *G1;
    int* degp;
    cudaGetSymbolAddress((void**)&H, g_H);
    cudaGetSymbolAddress((void**)&S, g_S);
    cudaGetSymbolAddress((void**)&C1, g_C1);
    cudaGetSymbolAddress((void**)&Wc, g_Wcat);
    cudaGetSymbolAddress((void**)&G1, g_G1);
    cudaGetSymbolAddress((void**)&degp, g_deg);

    // weight prep + CSR build
    wcat_kernel<<<(int)(((size_t)NLAYERS * HID * 2 * HID + 255) / 256), 256>>>(W1);
    zero_deg_kernel<<<(NPAD + 255) / 256, 256>>>();
    hist_kernel<<<(EDGES + 255) / 256, 256>>>(ei);
    scan_kernel<<<1, 1024>>>();
    scatter_kernel<<<(EDGES + 255) / 256, 256>>>(ei);

    // initial embedding
    proj_kernel<<<NPAD, 256>>>(x, proj_w);

    // layers
    for (int l = 0; l < NLAYERS; l++) {
        gemm_tf32_kernel<<<dim3(2 * HID / 128, NPAD / 128), 128>>>(
            H, Wc + (size_t)l * HID * 2 * HID, C1, HID, 2 * HID, 0, nullptr, nullptr);
        edge_agg_kernel<<<NPAD, 256>>>(b1 + (size_t)l * HID);
        gemm_tf32_kernel<<<dim3(HID / 128, NPAD / 128), 128>>>(
            S, W2 + (size_t)l * HID * HID, H, HID, HID, 2, b2 + (size_t)l * HID, degp);
    }

    // ghost hidden: G1 = relu(h @ gw1 + gb1)
    gemm_tf32_kernel<<<dim3(256 / 128, NPAD / 128), 128>>>(
        H, gw1, G1, HID, 256, 3, gb1, nullptr);

    // heads + output
    final_kernel<<<NNODES, 256>>>(gw2, gb2, sw, sb, out);

    (void)in_sizes; (void)n_in; (void)out_size;
}